// round 14
// baseline (speedup 1.0000x reference)
#include <cuda_runtime.h>
#include <cstdint>

// ---------------------------------------------------------------------------
// C=12, L=32, D=32, NOUT=2. Counts are int32 on device (JAX x64-off).
// Single fused kernel (replay-safe counter protocol):
//   streaming blocks : per-read q[r][2] = W2_s . relu(W x_r + b) sum over L
//                      cp.async 3-stage pipeline, unrolled x3 (compile-time
//                      stages), per-j tf32 conversion to cut live registers.
//   scan blocks      : global count offsets (hidden under the stream)
//   phase2 blocks    : dispatched last; spin on producer counter, then
//                      warp-per-allele ragged reduce + normalize + bias.
// __launch_bounds__(256,5): 51 regs -> 5 blocks/SM (was 61 regs / 4 blocks).
// ---------------------------------------------------------------------------

#define MAXR 131072
#define MAXA 16384
#define GX   1024              // streaming blocks per source
__device__ float2 g_q0[MAXR];
__device__ float2 g_q1[MAXR];
__device__ int g_loc0[MAXA];   // GLOBAL exclusive offset per allele
__device__ int g_loc1[MAXA];
__device__ int g_ctr1;         // producers done (streaming + scan)
__device__ int g_ctr2;         // phase2 blocks done

__device__ __forceinline__ uint32_t f2tf32(float f) {
    uint32_t u;
    asm("cvt.rna.tf32.f32 %0, %1;" : "=r"(u) : "f"(f));
    return u;
}

__device__ __forceinline__ void mma_tf32(float c[4], const uint32_t a[4],
                                         uint32_t b0, uint32_t b1) {
    asm volatile(
        "mma.sync.aligned.m16n8k8.row.col.f32.tf32.tf32.f32 "
        "{%0,%1,%2,%3},{%4,%5,%6,%7},{%8,%9},{%0,%1,%2,%3};"
        : "+f"(c[0]), "+f"(c[1]), "+f"(c[2]), "+f"(c[3])
        : "r"(a[0]), "r"(a[1]), "r"(a[2]), "r"(a[3]), "r"(b0), "r"(b1));
}

__device__ __forceinline__ void cp16(uint32_t smem_addr, const void* g) {
    asm volatile("cp.async.ca.shared.global [%0], [%1], 16;"
                 :: "r"(smem_addr), "l"(g));
}

// shared memory overlay: streaming pipeline buffer vs scan arrays
union SmemU {
    float4 buf[8][3][96];      // 36864 B
    struct { int s0[256]; int s1[256]; } scan;
};

// ---------------------------------------------------------------------------
// grid.x = GX + nch + P2B, grid.y = 2.
//   y any, x <  GX          : stream source y
//   y==0,  GX <= x < GX+nch : scan chunk (x-GX)
//   y==1,  x >= GX+nch      : phase2 block (x-GX-nch)  [dispatched last]
// ---------------------------------------------------------------------------
__global__ __launch_bounds__(256, 5) void rc_fused(
    const float* __restrict__ t0, const float* __restrict__ t1,
    const float* __restrict__ W0, const float* __restrict__ b0,
    const float* __restrict__ W1, const float* __restrict__ b1,
    const float* __restrict__ W2,
    const int* __restrict__ cnt0, const int* __restrict__ cnt1,
    const float* __restrict__ dm0, const float* __restrict__ dm1,
    const float* __restrict__ b2, float* __restrict__ out,
    int R, int A, int nch, int S, int P2B)
{
    const int tid = threadIdx.x;
    __shared__ SmemU sm;

    if (blockIdx.x >= GX) {
        const int xs = blockIdx.x - GX;
        // ------------------- scan blocks (y==0) -------------------
        if (xs < nch) {
            if (blockIdx.y != 0) return;
            int* s0 = sm.scan.s0;
            int* s1 = sm.scan.s1;
            const int chunk = xs;
            int b0r = 0, b1r = 0;
            for (int j = tid; j < chunk * 256; j += 256) {
                b0r += cnt0[j]; b1r += cnt1[j];
            }
            s0[tid] = b0r; s1[tid] = b1r;
            __syncthreads();
            #pragma unroll
            for (int o = 128; o; o >>= 1) {
                if (tid < o) { s0[tid] += s0[tid + o]; s1[tid] += s1[tid + o]; }
                __syncthreads();
            }
            const int base0 = s0[0], base1 = s1[0];
            __syncthreads();
            const int a = chunk * 256 + tid;
            const int v0 = (a < A) ? cnt0[a] : 0;
            const int v1 = (a < A) ? cnt1[a] : 0;
            s0[tid] = v0; s1[tid] = v1;
            __syncthreads();
            #pragma unroll
            for (int o = 1; o < 256; o <<= 1) {
                int p0 = (tid >= o) ? s0[tid - o] : 0;
                int p1 = (tid >= o) ? s1[tid - o] : 0;
                __syncthreads();
                s0[tid] += p0; s1[tid] += p1;
                __syncthreads();
            }
            if (a < A) {
                g_loc0[a] = base0 + s0[tid] - v0;
                g_loc1[a] = base1 + s1[tid] - v1;
            }
            __threadfence();
            __syncthreads();
            if (tid == 0) atomicAdd(&g_ctr1, 1);
            return;
        }
        // ------------------- phase2 blocks (y==1) -------------------
        if (blockIdx.y != 1) return;
        const int p2 = xs - nch;

        if (tid == 0) {
            while (*(volatile int*)&g_ctr1 < S) __nanosleep(200);
        }
        __syncthreads();
        __threadfence();   // acquire

        const int wid = tid >> 5, lane = tid & 31;
        const int a = p2 * 8 + wid;
        if (a < A) {
            const int off0 = g_loc0[a];
            const int off1 = g_loc1[a];
            const int c0 = cnt0[a], c1 = cnt1[a];

            float s00 = 0.f, s01 = 0.f, s10 = 0.f, s11 = 0.f;
            for (int i = lane; i < c0; i += 32) {
                float2 v = g_q0[off0 + i]; s00 += v.x; s01 += v.y;
            }
            for (int i = lane; i < c1; i += 32) {
                float2 v = g_q1[off1 + i]; s10 += v.x; s11 += v.y;
            }
            s00 += __shfl_xor_sync(0xffffffffu, s00, 8);
            s01 += __shfl_xor_sync(0xffffffffu, s01, 8);
            s10 += __shfl_xor_sync(0xffffffffu, s10, 8);
            s11 += __shfl_xor_sync(0xffffffffu, s11, 8);
            s00 += __shfl_xor_sync(0xffffffffu, s00, 16);
            s01 += __shfl_xor_sync(0xffffffffu, s01, 16);
            s10 += __shfl_xor_sync(0xffffffffu, s10, 16);
            s11 += __shfl_xor_sync(0xffffffffu, s11, 16);
            const int g = lane >> 3;
            float u = (g == 0) ? s00 : (g == 1) ? s01 : (g == 2) ? s10 : s11;
            u += __shfl_xor_sync(0xffffffffu, u, 1);
            u += __shfl_xor_sync(0xffffffffu, u, 2);
            u += __shfl_xor_sync(0xffffffffu, u, 4);
            float v2 = __shfl_sync(0xffffffffu, u, (lane & 15) + 16);
            if ((lane & 7) == 0 && lane < 16) {
                const float n0 = 1.0f / (dm0[a] * 32.f);
                const float n1 = 1.0f / (dm1[a] * 32.f);
                out[2 * a + (lane >> 3)] = b2[lane >> 3] + u * n0 + v2 * n1;
            }
        }
        __threadfence();
        __syncthreads();
        if (tid == 0) {
            int v = atomicAdd(&g_ctr2, 1);
            if (v == P2B - 1) {            // last phase2 block: reset state
                g_ctr1 = 0;
                g_ctr2 = 0;
                __threadfence();
            }
        }
        return;
    }

    // ------------------- streaming blocks -------------------
    const int s = blockIdx.y;
    const float* T  = s ? t1 : t0;
    const float* W  = s ? W1 : W0;
    const float* Bv = s ? b1 : b0;
    float* OutF     = s ? (float*)g_q1 : (float*)g_q0;

    const int wid  = tid >> 5, lane = tid & 31;
    const int qp   = lane >> 2, rp = lane & 3;
    const int g    = lane >> 3, h = lane & 7;

    uint32_t af[2][2][4];
    #pragma unroll
    for (int m = 0; m < 2; m++) {
        int r0 = qp + 16 * m, r1 = r0 + 8;
        af[m][0][0] = f2tf32(W[r0 * 12 + rp]);
        af[m][0][1] = f2tf32(W[r1 * 12 + rp]);
        af[m][0][2] = f2tf32(W[r0 * 12 + rp + 4]);
        af[m][0][3] = f2tf32(W[r1 * 12 + rp + 4]);
        af[m][1][0] = f2tf32(W[r0 * 12 + rp + 8]);
        af[m][1][1] = f2tf32(W[r1 * 12 + rp + 8]);
        af[m][1][2] = (rp == 0) ? f2tf32(Bv[r0]) : 0u;
        af[m][1][3] = (rp == 0) ? f2tf32(Bv[r1]) : 0u;
    }
    const uint32_t bk1 = (rp == 0) ? f2tf32(1.0f) : 0u;

    float w2a[4], w2b[4];
    #pragma unroll
    for (int i = 0; i < 4; i++) {
        w2a[i] = W2[s * 32 + 8 * i + qp];
        w2b[i] = W2[64 + s * 32 + 8 * i + qp];
    }

    const int sw_st = h ^ (2 * g);
    const int sts0 = g * 8 + sw_st, sts1 = (g + 4) * 8 + sw_st,
              sts2 = (g + 8) * 8 + sw_st;
    const int sw_ld = qp ^ (2 * rp);
    const int lds0 = rp * 8 + sw_ld, lds1 = (rp + 4) * 8 + sw_ld,
              lds2 = (rp + 8) * 8 + sw_ld;

    uint32_t dstc[3];
    #pragma unroll
    for (int st = 0; st < 3; st++)
        dstc[st] = (uint32_t)__cvta_generic_to_shared(&sm.buf[wid][st][sts0]);
    const int d1 = (sts1 - sts0) * 16;
    const int d2 = (sts2 - sts0) * 16;

    const int WT = GX * 8;
    const int r0w = blockIdx.x * 8 + wid;
    const int goff = g * 8 + h;
    const float4* T4 = (const float4*)T;

    // prologue: stages 0,1 for reads r0w, r0w+WT
    #pragma unroll
    for (int st = 0; st < 2; st++) {
        int rr = r0w + st * WT;
        if (rr < R) {
            const float4* p = T4 + (size_t)rr * 96 + goff;
            cp16(dstc[st], p);
            cp16(dstc[st] + d1, p + 32);
            cp16(dstc[st] + d2, p + 64);
        }
        asm volatile("cp.async.commit_group;" ::: "memory");
    }

    int r = r0w;
    const float4* psrc = T4 + (size_t)(r0w + 2 * WT) * 96 + goff;

    while (r < R) {
        #pragma unroll
        for (int s3 = 0; s3 < 3; s3++) {
            if (r < R) {
                const int pf = (s3 + 2) % 3;        // compile-time
                if (r + 2 * WT < R) {
                    cp16(dstc[pf], psrc);
                    cp16(dstc[pf] + d1, psrc + 32);
                    cp16(dstc[pf] + d2, psrc + 64);
                }
                asm volatile("cp.async.commit_group;" ::: "memory");
                asm volatile("cp.async.wait_group 2;" ::: "memory");
                __syncwarp();

                const float4* B = sm.buf[wid][s3];   // compile-time stage
                float4 x0 = B[lds0], x1 = B[lds1], x2 = B[lds2];
                const float a0[4] = {x0.x, x0.y, x0.z, x0.w};
                const float a1[4] = {x1.x, x1.y, x1.z, x1.w};
                const float a2[4] = {x2.x, x2.y, x2.z, x2.w};

                float acc[4] = {0.f, 0.f, 0.f, 0.f};
                #pragma unroll
                for (int j = 0; j < 4; j++) {
                    const uint32_t bb0 = f2tf32(a0[j]);
                    const uint32_t bb1 = f2tf32(a1[j]);
                    const uint32_t bb2 = f2tf32(a2[j]);
                    #pragma unroll
                    for (int m = 0; m < 2; m++) {
                        float c[4] = {0.f, 0.f, 0.f, 0.f};
                        mma_tf32(c, af[m][0], bb0, bb1);
                        mma_tf32(c, af[m][1], bb2, bk1);
                        acc[2 * m]     += fmaxf(c[0], 0.f) + fmaxf(c[1], 0.f);
                        acc[2 * m + 1] += fmaxf(c[2], 0.f) + fmaxf(c[3], 0.f);
                    }
                }
                float q0 = acc[0] * w2a[0] + acc[1] * w2a[1]
                         + acc[2] * w2a[2] + acc[3] * w2a[3];
                float q1 = acc[0] * w2b[0] + acc[1] * w2b[1]
                         + acc[2] * w2b[2] + acc[3] * w2b[3];
                q0 += __shfl_xor_sync(0xffffffffu, q0, 16);
                q1 += __shfl_xor_sync(0xffffffffu, q1, 16);
                float u = (lane < 16) ? q0 : q1;
                u += __shfl_xor_sync(0xffffffffu, u, 1);
                u += __shfl_xor_sync(0xffffffffu, u, 2);
                u += __shfl_xor_sync(0xffffffffu, u, 4);
                u += __shfl_xor_sync(0xffffffffu, u, 8);
                if ((lane & 15) == 0) OutF[2 * r + (lane >> 4)] = u;
            }
            r += WT;
            psrc += (size_t)WT * 96;
        }
    }

    __threadfence();
    __syncthreads();
    if (tid == 0) atomicAdd(&g_ctr1, 1);
}

// ---------------------------------------------------------------------------
extern "C" void kernel_launch(void* const* d_in, const int* in_sizes, int n_in,
                              void* d_out, int out_size) {
    const float* t0  = (const float*)d_in[0];
    const float* t1  = (const float*)d_in[1];
    const float* W0  = (const float*)d_in[2];
    const float* b0  = (const float*)d_in[3];
    const float* W1  = (const float*)d_in[4];
    const float* b1  = (const float*)d_in[5];
    const float* W2  = (const float*)d_in[6];
    const float* b2  = (const float*)d_in[7];
    const int*   c0  = (const int*)d_in[8];
    const int*   c1  = (const int*)d_in[9];
    const float* dm0 = (const float*)d_in[11];
    const float* dm1 = (const float*)d_in[12];
    float* out = (float*)d_out;

    const int A = in_sizes[8];
    const int R = in_sizes[0] / 384;   // reads per source (C*L = 384)
    const int nch = (A + 255) / 256;
    const int P2B = (A + 7) / 8;       // phase2 blocks
    const int S   = 2 * GX + nch;      // producer blocks to wait for

    dim3 grid(GX + nch + P2B, 2);
    rc_fused<<<grid, 256>>>(t0, t1, W0, b0, W1, b1, W2, c0, c1,
                            dm0, dm1, b2, out, R, A, nch, S, P2B);
}

// round 15
// speedup vs baseline: 1.1468x; 1.1468x over previous
#include <cuda_runtime.h>
#include <cstdint>

// ---------------------------------------------------------------------------
// C=12, L=32, D=32, NOUT=2. Counts are int32 on device (JAX x64-off).
// Single fused kernel, 1D grid (replay-safe counter protocol):
//   x < 2*GX          : streaming block, source = x&1, bx = x>>1
//   2*GX <= x < +nch  : scan chunk (global count offsets)
//   x >= 2*GX+nch     : phase2 (dispatched last; spins on producer counter)
// GX=592 -> 1184 streaming blocks = exactly 2 waves at 4 blocks/SM (148 SMs).
// Streaming path = round-13 measured-best (batched cvt, x3 unroll).
// ---------------------------------------------------------------------------

#define MAXR 131072
#define MAXA 16384
#define GX   592               // streaming blocks per source
__device__ float2 g_q0[MAXR];
__device__ float2 g_q1[MAXR];
__device__ int g_loc0[MAXA];   // GLOBAL exclusive offset per allele
__device__ int g_loc1[MAXA];
__device__ int g_ctr1;         // producers done (streaming + scan)
__device__ int g_ctr2;         // phase2 blocks done

__device__ __forceinline__ uint32_t f2tf32(float f) {
    uint32_t u;
    asm("cvt.rna.tf32.f32 %0, %1;" : "=r"(u) : "f"(f));
    return u;
}

__device__ __forceinline__ void mma_tf32(float c[4], const uint32_t a[4],
                                         uint32_t b0, uint32_t b1) {
    asm volatile(
        "mma.sync.aligned.m16n8k8.row.col.f32.tf32.tf32.f32 "
        "{%0,%1,%2,%3},{%4,%5,%6,%7},{%8,%9},{%0,%1,%2,%3};"
        : "+f"(c[0]), "+f"(c[1]), "+f"(c[2]), "+f"(c[3])
        : "r"(a[0]), "r"(a[1]), "r"(a[2]), "r"(a[3]), "r"(b0), "r"(b1));
}

__device__ __forceinline__ void cp16(uint32_t smem_addr, const void* g) {
    asm volatile("cp.async.ca.shared.global [%0], [%1], 16;"
                 :: "r"(smem_addr), "l"(g));
}

__global__ __launch_bounds__(256) void rc_fused(
    const float* __restrict__ t0, const float* __restrict__ t1,
    const float* __restrict__ W0, const float* __restrict__ b0,
    const float* __restrict__ W1, const float* __restrict__ b1,
    const float* __restrict__ W2,
    const int* __restrict__ cnt0, const int* __restrict__ cnt1,
    const float* __restrict__ dm0, const float* __restrict__ dm1,
    const float* __restrict__ b2, float* __restrict__ out,
    int R, int A, int nch, int S, int P2B)
{
    const int tid = threadIdx.x;

    if (blockIdx.x >= 2 * GX) {
        const int xs = blockIdx.x - 2 * GX;
        // ------------------- scan blocks -------------------
        if (xs < nch) {
            const int chunk = xs;
            __shared__ int s0[256], s1[256];
            int b0r = 0, b1r = 0;
            for (int j = tid; j < chunk * 256; j += 256) {
                b0r += cnt0[j]; b1r += cnt1[j];
            }
            s0[tid] = b0r; s1[tid] = b1r;
            __syncthreads();
            #pragma unroll
            for (int o = 128; o; o >>= 1) {
                if (tid < o) { s0[tid] += s0[tid + o]; s1[tid] += s1[tid + o]; }
                __syncthreads();
            }
            const int base0 = s0[0], base1 = s1[0];
            __syncthreads();
            const int a = chunk * 256 + tid;
            const int v0 = (a < A) ? cnt0[a] : 0;
            const int v1 = (a < A) ? cnt1[a] : 0;
            s0[tid] = v0; s1[tid] = v1;
            __syncthreads();
            #pragma unroll
            for (int o = 1; o < 256; o <<= 1) {
                int p0 = (tid >= o) ? s0[tid - o] : 0;
                int p1 = (tid >= o) ? s1[tid - o] : 0;
                __syncthreads();
                s0[tid] += p0; s1[tid] += p1;
                __syncthreads();
            }
            if (a < A) {
                g_loc0[a] = base0 + s0[tid] - v0;
                g_loc1[a] = base1 + s1[tid] - v1;
            }
            __threadfence();
            __syncthreads();
            if (tid == 0) atomicAdd(&g_ctr1, 1);
            return;
        }
        // ------------------- phase2 blocks (dispatched last) ---------------
        const int p2 = xs - nch;

        if (tid == 0) {
            while (*(volatile int*)&g_ctr1 < S) __nanosleep(200);
        }
        __syncthreads();
        __threadfence();   // acquire

        const int wid = tid >> 5, lane = tid & 31;
        const int a = p2 * 8 + wid;
        if (a < A) {
            const int off0 = g_loc0[a];
            const int off1 = g_loc1[a];
            const int c0 = cnt0[a], c1 = cnt1[a];

            float s00 = 0.f, s01 = 0.f, s10 = 0.f, s11 = 0.f;
            for (int i = lane; i < c0; i += 32) {
                float2 v = g_q0[off0 + i]; s00 += v.x; s01 += v.y;
            }
            for (int i = lane; i < c1; i += 32) {
                float2 v = g_q1[off1 + i]; s10 += v.x; s11 += v.y;
            }
            s00 += __shfl_xor_sync(0xffffffffu, s00, 8);
            s01 += __shfl_xor_sync(0xffffffffu, s01, 8);
            s10 += __shfl_xor_sync(0xffffffffu, s10, 8);
            s11 += __shfl_xor_sync(0xffffffffu, s11, 8);
            s00 += __shfl_xor_sync(0xffffffffu, s00, 16);
            s01 += __shfl_xor_sync(0xffffffffu, s01, 16);
            s10 += __shfl_xor_sync(0xffffffffu, s10, 16);
            s11 += __shfl_xor_sync(0xffffffffu, s11, 16);
            const int g = lane >> 3;
            float u = (g == 0) ? s00 : (g == 1) ? s01 : (g == 2) ? s10 : s11;
            u += __shfl_xor_sync(0xffffffffu, u, 1);
            u += __shfl_xor_sync(0xffffffffu, u, 2);
            u += __shfl_xor_sync(0xffffffffu, u, 4);
            float v2 = __shfl_sync(0xffffffffu, u, (lane & 15) + 16);
            if ((lane & 7) == 0 && lane < 16) {
                const float n0 = 1.0f / (dm0[a] * 32.f);
                const float n1 = 1.0f / (dm1[a] * 32.f);
                out[2 * a + (lane >> 3)] = b2[lane >> 3] + u * n0 + v2 * n1;
            }
        }
        __threadfence();
        __syncthreads();
        if (tid == 0) {
            int v = atomicAdd(&g_ctr2, 1);
            if (v == P2B - 1) {            // last phase2 block: reset state
                g_ctr1 = 0;
                g_ctr2 = 0;
                __threadfence();
            }
        }
        return;
    }

    // ------------------- streaming blocks (round-13 path) -------------------
    const int s  = blockIdx.x & 1;         // interleave sources across SMs
    const int bx = blockIdx.x >> 1;
    const float* T  = s ? t1 : t0;
    const float* W  = s ? W1 : W0;
    const float* Bv = s ? b1 : b0;
    float* OutF     = s ? (float*)g_q1 : (float*)g_q0;

    const int wid  = tid >> 5, lane = tid & 31;
    const int qp   = lane >> 2, rp = lane & 3;
    const int g    = lane >> 3, h = lane & 7;

    __shared__ float4 buf[8][3][96];

    uint32_t af[2][2][4];
    #pragma unroll
    for (int m = 0; m < 2; m++) {
        int r0 = qp + 16 * m, r1 = r0 + 8;
        af[m][0][0] = f2tf32(W[r0 * 12 + rp]);
        af[m][0][1] = f2tf32(W[r1 * 12 + rp]);
        af[m][0][2] = f2tf32(W[r0 * 12 + rp + 4]);
        af[m][0][3] = f2tf32(W[r1 * 12 + rp + 4]);
        af[m][1][0] = f2tf32(W[r0 * 12 + rp + 8]);
        af[m][1][1] = f2tf32(W[r1 * 12 + rp + 8]);
        af[m][1][2] = (rp == 0) ? f2tf32(Bv[r0]) : 0u;
        af[m][1][3] = (rp == 0) ? f2tf32(Bv[r1]) : 0u;
    }
    const uint32_t bk1 = (rp == 0) ? f2tf32(1.0f) : 0u;

    float w2a[4], w2b[4];
    #pragma unroll
    for (int i = 0; i < 4; i++) {
        w2a[i] = W2[s * 32 + 8 * i + qp];
        w2b[i] = W2[64 + s * 32 + 8 * i + qp];
    }

    const int sw_st = h ^ (2 * g);
    const int sts0 = g * 8 + sw_st, sts1 = (g + 4) * 8 + sw_st,
              sts2 = (g + 8) * 8 + sw_st;
    const int sw_ld = qp ^ (2 * rp);
    const int lds0 = rp * 8 + sw_ld, lds1 = (rp + 4) * 8 + sw_ld,
              lds2 = (rp + 8) * 8 + sw_ld;

    uint32_t dstc[3];
    #pragma unroll
    for (int st = 0; st < 3; st++)
        dstc[st] = (uint32_t)__cvta_generic_to_shared(&buf[wid][st][sts0]);
    const int d1 = (sts1 - sts0) * 16;
    const int d2 = (sts2 - sts0) * 16;

    const int WT = GX * 8;
    const int r0w = bx * 8 + wid;
    const int goff = g * 8 + h;
    const float4* T4 = (const float4*)T;

    // prologue: stages 0,1 for reads r0w, r0w+WT
    #pragma unroll
    for (int st = 0; st < 2; st++) {
        int rr = r0w + st * WT;
        if (rr < R) {
            const float4* p = T4 + (size_t)rr * 96 + goff;
            cp16(dstc[st], p);
            cp16(dstc[st] + d1, p + 32);
            cp16(dstc[st] + d2, p + 64);
        }
        asm volatile("cp.async.commit_group;" ::: "memory");
    }

    int r = r0w;
    const float4* psrc = T4 + (size_t)(r0w + 2 * WT) * 96 + goff;

    while (r < R) {
        #pragma unroll
        for (int s3 = 0; s3 < 3; s3++) {
            if (r < R) {
                const int pf = (s3 + 2) % 3;        // compile-time
                if (r + 2 * WT < R) {
                    cp16(dstc[pf], psrc);
                    cp16(dstc[pf] + d1, psrc + 32);
                    cp16(dstc[pf] + d2, psrc + 64);
                }
                asm volatile("cp.async.commit_group;" ::: "memory");
                asm volatile("cp.async.wait_group 2;" ::: "memory");
                __syncwarp();

                const float4* B = buf[wid][s3];      // compile-time stage
                float4 x0 = B[lds0], x1 = B[lds1], x2 = B[lds2];
                uint32_t u0[4] = {f2tf32(x0.x), f2tf32(x0.y),
                                  f2tf32(x0.z), f2tf32(x0.w)};
                uint32_t u1[4] = {f2tf32(x1.x), f2tf32(x1.y),
                                  f2tf32(x1.z), f2tf32(x1.w)};
                uint32_t u2[4] = {f2tf32(x2.x), f2tf32(x2.y),
                                  f2tf32(x2.z), f2tf32(x2.w)};

                float acc[4] = {0.f, 0.f, 0.f, 0.f};
                #pragma unroll
                for (int j = 0; j < 4; j++) {
                    #pragma unroll
                    for (int m = 0; m < 2; m++) {
                        float c[4] = {0.f, 0.f, 0.f, 0.f};
                        mma_tf32(c, af[m][0], u0[j], u1[j]);
                        mma_tf32(c, af[m][1], u2[j], bk1);
                        acc[2 * m]     += fmaxf(c[0], 0.f) + fmaxf(c[1], 0.f);
                        acc[2 * m + 1] += fmaxf(c[2], 0.f) + fmaxf(c[3], 0.f);
                    }
                }
                float q0 = acc[0] * w2a[0] + acc[1] * w2a[1]
                         + acc[2] * w2a[2] + acc[3] * w2a[3];
                float q1 = acc[0] * w2b[0] + acc[1] * w2b[1]
                         + acc[2] * w2b[2] + acc[3] * w2b[3];
                q0 += __shfl_xor_sync(0xffffffffu, q0, 16);
                q1 += __shfl_xor_sync(0xffffffffu, q1, 16);
                float u = (lane < 16) ? q0 : q1;
                u += __shfl_xor_sync(0xffffffffu, u, 1);
                u += __shfl_xor_sync(0xffffffffu, u, 2);
                u += __shfl_xor_sync(0xffffffffu, u, 4);
                u += __shfl_xor_sync(0xffffffffu, u, 8);
                if ((lane & 15) == 0) OutF[2 * r + (lane >> 4)] = u;
            }
            r += WT;
            psrc += (size_t)WT * 96;
        }
    }

    __threadfence();
    __syncthreads();
    if (tid == 0) atomicAdd(&g_ctr1, 1);
}

// ---------------------------------------------------------------------------
extern "C" void kernel_launch(void* const* d_in, const int* in_sizes, int n_in,
                              void* d_out, int out_size) {
    const float* t0  = (const float*)d_in[0];
    const float* t1  = (const float*)d_in[1];
    const float* W0  = (const float*)d_in[2];
    const float* b0  = (const float*)d_in[3];
    const float* W1  = (const float*)d_in[4];
    const float* b1  = (const float*)d_in[5];
    const float* W2  = (const float*)d_in[6];
    const float* b2  = (const float*)d_in[7];
    const int*   c0  = (const int*)d_in[8];
    const int*   c1  = (const int*)d_in[9];
    const float* dm0 = (const float*)d_in[11];
    const float* dm1 = (const float*)d_in[12];
    float* out = (float*)d_out;

    const int A = in_sizes[8];
    const int R = in_sizes[0] / 384;   // reads per source (C*L = 384)
    const int nch = (A + 255) / 256;
    const int P2B = (A + 7) / 8;       // phase2 blocks
    const int S   = 2 * GX + nch;      // producer blocks to wait for

    dim3 grid(2 * GX + nch + P2B, 1);
    rc_fused<<<grid, 256>>>(t0, t1, W0, b0, W1, b1, W2, c0, c1,
                            dm0, dm1, b2, out, R, A, nch, S, P2B);
}